// round 1
// baseline (speedup 1.0000x reference)
#include <cuda_runtime.h>
#include <cstdint>

#define M_TOTAL 16384
#define N_TOTAL 4096
#define K_TOTAL 4096
#define NSLOT   8

#define BM 128
#define BN 128
#define BK 32
#define STAGES 3
#define PAD 4
#define TS (BK + PAD)   // smem row stride in floats = 36

// Scratch (allocation-free rule: __device__ globals)
__device__ float g_W[(size_t)N_TOTAL * K_TOTAL];
__device__ float g_b[N_TOTAL];

// ---------------------------------------------------------------------------
// Kernel 1: W = weight + sum_i (scale_i*wscale_i)*wq_i + (scale . wzp)
// HBM-bound: reads 512MB wq + 64MB weight, writes 64MB.
// ---------------------------------------------------------------------------
__global__ void compute_w_kernel(const float* __restrict__ weight,
                                 const int*   __restrict__ wq,
                                 const float* __restrict__ scale,
                                 const float* __restrict__ wscale,
                                 const int*   __restrict__ wzp) {
    const size_t nvec = (size_t)N_TOTAL * K_TOTAL / 4;
    size_t idx = (size_t)blockIdx.x * blockDim.x + threadIdx.x;
    if (idx >= nvec) return;

    float c[NSLOT];
    float z = 0.f;
#pragma unroll
    for (int i = 0; i < NSLOT; i++) {
        float s = scale[i];
        c[i] = s * wscale[i];
        z += s * (float)wzp[i];
    }

    float4 w = reinterpret_cast<const float4*>(weight)[idx];
    float ax = w.x + z, ay = w.y + z, az = w.z + z, aw = w.w + z;
#pragma unroll
    for (int i = 0; i < NSLOT; i++) {
        int4 q = reinterpret_cast<const int4*>(wq)[(size_t)i * nvec + idx];
        ax += c[i] * (float)q.x;
        ay += c[i] * (float)q.y;
        az += c[i] * (float)q.z;
        aw += c[i] * (float)q.w;
    }
    reinterpret_cast<float4*>(g_W)[idx] = make_float4(ax, ay, az, aw);
}

// ---------------------------------------------------------------------------
// Kernel 2: b = bias + sum_i scale_i*(bscale_i*bq_i + bzp_i)
// ---------------------------------------------------------------------------
__global__ void compute_b_kernel(const float* __restrict__ bias,
                                 const float* __restrict__ scale,
                                 const int*   __restrict__ bq,
                                 const float* __restrict__ bscale,
                                 const int*   __restrict__ bzp) {
    int j = blockIdx.x * blockDim.x + threadIdx.x;
    if (j >= N_TOTAL) return;
    float acc = bias[j];
#pragma unroll
    for (int i = 0; i < NSLOT; i++) {
        acc += scale[i] * (bscale[i] * (float)bq[i * N_TOTAL + j] + (float)bzp[i]);
    }
    g_b[j] = acc;
}

// ---------------------------------------------------------------------------
// Kernel 3: OUT[m,n] = sum_k X[m,k] * W[n,k] + b[n]
// TN GEMM, tf32 mma.sync m16n8k8, 128x128x32 CTA tile, 3-stage cp.async.
// ---------------------------------------------------------------------------
__device__ __forceinline__ uint32_t f2tf32(float f) {
    uint32_t r;
    asm("cvt.rna.tf32.f32 %0, %1;" : "=r"(r) : "f"(f));
    return r;
}

extern __shared__ float smem_buf[];

__global__ void __launch_bounds__(256, 1)
gemm_tf32_kernel(const float* __restrict__ X, float* __restrict__ OUT) {
    const int tid  = threadIdx.x;
    const int warp = tid >> 5;
    const int lane = tid & 31;
    const int wm = warp >> 2;   // 0..1  (64 rows each)
    const int wn = warp & 3;    // 0..3  (32 cols each)
    const int bm = blockIdx.y * BM;
    const int bn = blockIdx.x * BN;

    float* As = smem_buf;                         // STAGES * BM * TS floats
    float* Bs = smem_buf + STAGES * BM * TS;      // STAGES * BN * TS floats

    // global->smem load mapping: 256 threads, 16B each, 4 passes per operand
    const int lrow = tid >> 3;        // 0..31
    const int lcol = (tid & 7) * 4;   // 0,4,...,28

    const float* a_base = X   + (size_t)(bm + lrow) * K_TOTAL + lcol;
    const float* b_base = g_W + (size_t)(bn + lrow) * K_TOTAL + lcol;

    auto issue_tile = [&](int t) {
        const int s = t % STAGES;
        const size_t kofs = (size_t)t * BK;
        float* a_dst = As + s * BM * TS + lrow * TS + lcol;
        float* b_dst = Bs + s * BN * TS + lrow * TS + lcol;
        const float* a_src = a_base + kofs;
        const float* b_src = b_base + kofs;
#pragma unroll
        for (int p = 0; p < 4; p++) {
            uint32_t sa = (uint32_t)__cvta_generic_to_shared(a_dst + p * 32 * TS);
            asm volatile("cp.async.cg.shared.global [%0], [%1], 16;\n"
                         :: "r"(sa), "l"(a_src + (size_t)p * 32 * K_TOTAL));
            uint32_t sb = (uint32_t)__cvta_generic_to_shared(b_dst + p * 32 * TS);
            asm volatile("cp.async.cg.shared.global [%0], [%1], 16;\n"
                         :: "r"(sb), "l"(b_src + (size_t)p * 32 * K_TOTAL));
        }
    };

    float acc[4][4][4];
#pragma unroll
    for (int mt = 0; mt < 4; mt++)
#pragma unroll
        for (int nt = 0; nt < 4; nt++)
#pragma unroll
            for (int r = 0; r < 4; r++) acc[mt][nt][r] = 0.f;

    const int KT = K_TOTAL / BK;   // 128

    // prologue: prefetch STAGES-1 tiles
#pragma unroll
    for (int t = 0; t < STAGES - 1; t++) {
        issue_tile(t);
        asm volatile("cp.async.commit_group;\n");
    }

    const int ar = lane >> 2;   // 0..7
    const int ac = lane & 3;    // 0..3

    for (int t = 0; t < KT; t++) {
        asm volatile("cp.async.wait_group %0;\n" :: "n"(STAGES - 2));
        __syncthreads();

        if (t + STAGES - 1 < KT) issue_tile(t + STAGES - 1);
        asm volatile("cp.async.commit_group;\n");

        const float* a_s = As + (t % STAGES) * BM * TS + (wm * 64) * TS;
        const float* b_s = Bs + (t % STAGES) * BN * TS + (wn * 32) * TS;

#pragma unroll
        for (int ks = 0; ks < 4; ks++) {
            const int k0 = ks * 8;
            uint32_t afr[4][4];
#pragma unroll
            for (int mt = 0; mt < 4; mt++) {
                const float* ap = a_s + (mt * 16 + ar) * TS + k0 + ac;
                afr[mt][0] = f2tf32(ap[0]);
                afr[mt][1] = f2tf32(ap[8 * TS]);
                afr[mt][2] = f2tf32(ap[4]);
                afr[mt][3] = f2tf32(ap[8 * TS + 4]);
            }
            uint32_t bfr[4][2];
#pragma unroll
            for (int nt = 0; nt < 4; nt++) {
                const float* bp = b_s + (nt * 8 + ar) * TS + k0 + ac;
                bfr[nt][0] = f2tf32(bp[0]);
                bfr[nt][1] = f2tf32(bp[4]);
            }
#pragma unroll
            for (int mt = 0; mt < 4; mt++) {
#pragma unroll
                for (int nt = 0; nt < 4; nt++) {
                    asm volatile(
                        "mma.sync.aligned.m16n8k8.row.col.f32.tf32.tf32.f32 "
                        "{%0,%1,%2,%3}, {%4,%5,%6,%7}, {%8,%9}, {%0,%1,%2,%3};\n"
                        : "+f"(acc[mt][nt][0]), "+f"(acc[mt][nt][1]),
                          "+f"(acc[mt][nt][2]), "+f"(acc[mt][nt][3])
                        : "r"(afr[mt][0]), "r"(afr[mt][1]),
                          "r"(afr[mt][2]), "r"(afr[mt][3]),
                          "r"(bfr[nt][0]), "r"(bfr[nt][1]));
                }
            }
        }
        __syncthreads();
    }

    // epilogue: add bias, write out (float2 pairs, C fragment layout of m16n8)
#pragma unroll
    for (int mt = 0; mt < 4; mt++) {
        const int row0 = bm + wm * 64 + mt * 16 + (lane >> 2);
#pragma unroll
        for (int nt = 0; nt < 4; nt++) {
            const int col = bn + wn * 32 + nt * 8 + (lane & 3) * 2;
            const float b0 = g_b[col];
            const float b1 = g_b[col + 1];
            float2 v0 = make_float2(acc[mt][nt][0] + b0, acc[mt][nt][1] + b1);
            float2 v1 = make_float2(acc[mt][nt][2] + b0, acc[mt][nt][3] + b1);
            *reinterpret_cast<float2*>(OUT + (size_t)row0 * N_TOTAL + col) = v0;
            *reinterpret_cast<float2*>(OUT + (size_t)(row0 + 8) * N_TOTAL + col) = v1;
        }
    }
}

// ---------------------------------------------------------------------------
extern "C" void kernel_launch(void* const* d_in, const int* in_sizes, int n_in,
                              void* d_out, int out_size) {
    const float* x      = (const float*)d_in[0];
    const float* weight = (const float*)d_in[1];
    const float* bias   = (const float*)d_in[2];
    const float* scale  = (const float*)d_in[3];
    const int*   wq     = (const int*)  d_in[4];
    const float* wscale = (const float*)d_in[5];
    const int*   wzp    = (const int*)  d_in[6];
    const int*   bq     = (const int*)  d_in[7];
    const float* bscale = (const float*)d_in[8];
    const int*   bzp    = (const int*)  d_in[9];
    float* out = (float*)d_out;

    // 1) dequant + fold into W (HBM-bound, ~0.1 ms)
    {
        const size_t nvec = (size_t)N_TOTAL * K_TOTAL / 4;
        int threads = 256;
        int blocks = (int)((nvec + threads - 1) / threads);
        compute_w_kernel<<<blocks, threads>>>(weight, wq, scale, wscale, wzp);
    }
    // 2) bias
    compute_b_kernel<<<(N_TOTAL + 255) / 256, 256>>>(bias, scale, bq, bscale, bzp);

    // 3) big TN GEMM
    {
        int smem_bytes = STAGES * (BM + BN) * TS * (int)sizeof(float);  // 110592
        cudaFuncSetAttribute(gemm_tf32_kernel,
                             cudaFuncAttributeMaxDynamicSharedMemorySize, smem_bytes);
        dim3 grid(N_TOTAL / BN, M_TOTAL / BM);   // (32, 128)
        gemm_tf32_kernel<<<grid, 256, smem_bytes>>>(x, out);
    }
}

// round 3
// speedup vs baseline: 1.0118x; 1.0118x over previous
#include <cuda_runtime.h>
#include <cstdint>

#define M_TOTAL 16384
#define N_TOTAL 4096
#define K_TOTAL 4096
#define NSLOT   8

#define BM 128
#define BN 256
#define BK 32
#define STAGES 3
#define PAD 4
#define TS (BK + PAD)   // 36 floats per smem row

// Scratch (allocation-free rule: __device__ globals)
__device__ float g_W[(size_t)N_TOTAL * K_TOTAL];   // dequantized + tf32-rounded W
__device__ float g_X[(size_t)M_TOTAL * K_TOTAL];   // tf32-rounded X
__device__ float g_b[N_TOTAL];

__device__ __forceinline__ float rne_tf32(float f) {
    uint32_t r;
    asm("cvt.rna.tf32.f32 %0, %1;" : "=r"(r) : "f"(f));
    return __uint_as_float(r);
}

// ---------------------------------------------------------------------------
// Kernel 1: W = tf32(weight + sum_i (scale_i*wscale_i)*wq_i + (scale . wzp))
// ---------------------------------------------------------------------------
__global__ void compute_w_kernel(const float* __restrict__ weight,
                                 const int*   __restrict__ wq,
                                 const float* __restrict__ scale,
                                 const float* __restrict__ wscale,
                                 const int*   __restrict__ wzp) {
    const size_t nvec = (size_t)N_TOTAL * K_TOTAL / 4;
    size_t idx = (size_t)blockIdx.x * blockDim.x + threadIdx.x;
    if (idx >= nvec) return;

    float c[NSLOT];
    float z = 0.f;
#pragma unroll
    for (int i = 0; i < NSLOT; i++) {
        float s = scale[i];
        c[i] = s * wscale[i];
        z += s * (float)wzp[i];
    }
    float4 w = reinterpret_cast<const float4*>(weight)[idx];
    float ax = w.x + z, ay = w.y + z, az = w.z + z, aw = w.w + z;
#pragma unroll
    for (int i = 0; i < NSLOT; i++) {
        int4 q = reinterpret_cast<const int4*>(wq)[(size_t)i * nvec + idx];
        ax += c[i] * (float)q.x;
        ay += c[i] * (float)q.y;
        az += c[i] * (float)q.z;
        aw += c[i] * (float)q.w;
    }
    reinterpret_cast<float4*>(g_W)[idx] =
        make_float4(rne_tf32(ax), rne_tf32(ay), rne_tf32(az), rne_tf32(aw));
}

// ---------------------------------------------------------------------------
// Kernel 1b: X rounded to tf32 (so the GEMM mainloop needs zero CVTs)
// ---------------------------------------------------------------------------
__global__ void round_x_kernel(const float* __restrict__ x) {
    const size_t nvec = (size_t)M_TOTAL * K_TOTAL / 4;
    size_t idx = (size_t)blockIdx.x * blockDim.x + threadIdx.x;
    if (idx >= nvec) return;
    float4 v = reinterpret_cast<const float4*>(x)[idx];
    reinterpret_cast<float4*>(g_X)[idx] =
        make_float4(rne_tf32(v.x), rne_tf32(v.y), rne_tf32(v.z), rne_tf32(v.w));
}

// ---------------------------------------------------------------------------
// Kernel 2: b = bias + sum_i scale_i*(bscale_i*bq_i + bzp_i)
// ---------------------------------------------------------------------------
__global__ void compute_b_kernel(const float* __restrict__ bias,
                                 const float* __restrict__ scale,
                                 const int*   __restrict__ bq,
                                 const float* __restrict__ bscale,
                                 const int*   __restrict__ bzp) {
    int j = blockIdx.x * blockDim.x + threadIdx.x;
    if (j >= N_TOTAL) return;
    float acc = bias[j];
#pragma unroll
    for (int i = 0; i < NSLOT; i++)
        acc += scale[i] * (bscale[i] * (float)bq[i * N_TOTAL + j] + (float)bzp[i]);
    g_b[j] = acc;
}

// ---------------------------------------------------------------------------
// Kernel 3: OUT[m,n] = sum_k X[m,k] * W[n,k] + b[n]
// tf32 mma.sync m16n8k8. CTA tile 128x256x32, warp tile 64x64, 8 warps,
// 3-stage cp.async pipeline. No CVT in the mainloop (operands pre-rounded).
// ---------------------------------------------------------------------------
extern __shared__ float smem_buf[];

__global__ void __launch_bounds__(256, 1)
gemm_tf32_kernel(float* __restrict__ OUT) {
    const int tid  = threadIdx.x;
    const int warp = tid >> 5;
    const int lane = tid & 31;
    const int wm = warp >> 2;   // 0..1 : 64 rows each
    const int wn = warp & 3;    // 0..3 : 64 cols each
    const int bm = blockIdx.y * BM;
    const int bn = blockIdx.x * BN;

    float* As = smem_buf;                         // STAGES * BM * TS
    float* Bs = smem_buf + STAGES * BM * TS;      // STAGES * BN * TS

    const int lrow = tid >> 3;        // 0..31
    const int lcol = (tid & 7) * 4;   // 0..28 step 4

    const float* a_base = g_X + (size_t)(bm + lrow) * K_TOTAL + lcol;
    const float* b_base = g_W + (size_t)(bn + lrow) * K_TOTAL + lcol;

    auto issue_tile = [&](int t) {
        const int s = t % STAGES;
        const size_t kofs = (size_t)t * BK;
        float* a_dst = As + s * BM * TS + lrow * TS + lcol;
        float* b_dst = Bs + s * BN * TS + lrow * TS + lcol;
        const float* a_src = a_base + kofs;
        const float* b_src = b_base + kofs;
#pragma unroll
        for (int p = 0; p < 4; p++) {
            uint32_t sa = (uint32_t)__cvta_generic_to_shared(a_dst + p * 32 * TS);
            asm volatile("cp.async.cg.shared.global [%0], [%1], 16;\n"
                         :: "r"(sa), "l"(a_src + (size_t)p * 32 * K_TOTAL));
        }
#pragma unroll
        for (int p = 0; p < 8; p++) {
            uint32_t sb = (uint32_t)__cvta_generic_to_shared(b_dst + p * 32 * TS);
            asm volatile("cp.async.cg.shared.global [%0], [%1], 16;\n"
                         :: "r"(sb), "l"(b_src + (size_t)p * 32 * K_TOTAL));
        }
    };

    float acc[4][8][4];
#pragma unroll
    for (int mt = 0; mt < 4; mt++)
#pragma unroll
        for (int nt = 0; nt < 8; nt++)
#pragma unroll
            for (int r = 0; r < 4; r++) acc[mt][nt][r] = 0.f;

    const int KT = K_TOTAL / BK;   // 128

#pragma unroll
    for (int t = 0; t < STAGES - 1; t++) {
        issue_tile(t);
        asm volatile("cp.async.commit_group;\n");
    }

    const int q = lane >> 2;   // 0..7 (row within 8)
    const int c = lane & 3;    // 0..3 (k within 4)

    for (int t = 0; t < KT; t++) {
        asm volatile("cp.async.wait_group %0;\n" :: "n"(STAGES - 2));
        __syncthreads();

        if (t + STAGES - 1 < KT) issue_tile(t + STAGES - 1);
        asm volatile("cp.async.commit_group;\n");

        const float* a_s = As + (t % STAGES) * BM * TS + (wm * 64) * TS;
        const float* b_s = Bs + (t % STAGES) * BN * TS + (wn * 64) * TS;

#pragma unroll
        for (int ks = 0; ks < 4; ks++) {
            const int k0 = ks * 8;
            uint32_t afr[4][4];
#pragma unroll
            for (int mt = 0; mt < 4; mt++) {
                const float* ap = a_s + (mt * 16 + q) * TS + k0 + c;
                afr[mt][0] = __float_as_uint(ap[0]);
                afr[mt][1] = __float_as_uint(ap[8 * TS]);
                afr[mt][2] = __float_as_uint(ap[4]);
                afr[mt][3] = __float_as_uint(ap[8 * TS + 4]);
            }
            uint32_t bfr[8][2];
#pragma unroll
            for (int nt = 0; nt < 8; nt++) {
                const float* bp = b_s + (nt * 8 + q) * TS + k0 + c;
                bfr[nt][0] = __float_as_uint(bp[0]);
                bfr[nt][1] = __float_as_uint(bp[4]);
            }
#pragma unroll
            for (int mt = 0; mt < 4; mt++) {
#pragma unroll
                for (int nt = 0; nt < 8; nt++) {
                    asm volatile(
                        "mma.sync.aligned.m16n8k8.row.col.f32.tf32.tf32.f32 "
                        "{%0,%1,%2,%3}, {%4,%5,%6,%7}, {%8,%9}, {%0,%1,%2,%3};\n"
                        : "+f"(acc[mt][nt][0]), "+f"(acc[mt][nt][1]),
                          "+f"(acc[mt][nt][2]), "+f"(acc[mt][nt][3])
                        : "r"(afr[mt][0]), "r"(afr[mt][1]),
                          "r"(afr[mt][2]), "r"(afr[mt][3]),
                          "r"(bfr[nt][0]), "r"(bfr[nt][1]));
                }
            }
        }
        __syncthreads();
    }

    // epilogue: bias + store (C fragment layout of m16n8)
#pragma unroll
    for (int mt = 0; mt < 4; mt++) {
        const int row0 = bm + wm * 64 + mt * 16 + q;
#pragma unroll
        for (int nt = 0; nt < 8; nt++) {
            const int col = bn + wn * 64 + nt * 8 + c * 2;
            const float b0 = g_b[col];
            const float b1 = g_b[col + 1];
            float2 v0 = make_float2(acc[mt][nt][0] + b0, acc[mt][nt][1] + b1);
            float2 v1 = make_float2(acc[mt][nt][2] + b0, acc[mt][nt][3] + b1);
            *reinterpret_cast<float2*>(OUT + (size_t)row0 * N_TOTAL + col) = v0;
            *reinterpret_cast<float2*>(OUT + (size_t)(row0 + 8) * N_TOTAL + col) = v1;
        }
    }
}

// ---------------------------------------------------------------------------
extern "C" void kernel_launch(void* const* d_in, const int* in_sizes, int n_in,
                              void* d_out, int out_size) {
    const float* x      = (const float*)d_in[0];
    const float* weight = (const float*)d_in[1];
    const float* bias   = (const float*)d_in[2];
    const float* scale  = (const float*)d_in[3];
    const int*   wq     = (const int*)  d_in[4];
    const float* wscale = (const float*)d_in[5];
    const int*   wzp    = (const int*)  d_in[6];
    const int*   bq     = (const int*)  d_in[7];
    const float* bscale = (const float*)d_in[8];
    const int*   bzp    = (const int*)  d_in[9];
    float* out = (float*)d_out;

    {
        const size_t nvec = (size_t)N_TOTAL * K_TOTAL / 4;
        compute_w_kernel<<<(int)((nvec + 255) / 256), 256>>>(weight, wq, scale, wscale, wzp);
    }
    {
        const size_t nvec = (size_t)M_TOTAL * K_TOTAL / 4;
        round_x_kernel<<<(int)((nvec + 255) / 256), 256>>>(x);
    }
    compute_b_kernel<<<(N_TOTAL + 255) / 256, 256>>>(bias, scale, bq, bscale, bzp);

    {
        int smem_bytes = STAGES * (BM + BN) * TS * (int)sizeof(float);  // 165888
        cudaFuncSetAttribute(gemm_tf32_kernel,
                             cudaFuncAttributeMaxDynamicSharedMemorySize, smem_bytes);
        dim3 grid(N_TOTAL / BN, M_TOTAL / BM);   // (16, 128)
        gemm_tf32_kernel<<<grid, 256, smem_bytes>>>(out);
    }
}

// round 4
// speedup vs baseline: 1.0692x; 1.0568x over previous
#include <cuda_runtime.h>
#include <cstdint>

#define M_TOTAL 16384
#define N_TOTAL 4096
#define K_TOTAL 4096
#define NSLOT   8

#define BM 128
#define BN 128
#define BK 32
#define STAGES 3
#define PAD 4
#define TS (BK + PAD)   // 36 floats per smem row (conflict-free LDS.32)

// Scratch (allocation-free rule: __device__ globals)
__device__ float g_W[(size_t)N_TOTAL * K_TOTAL];   // dequantized + tf32-rounded W
__device__ float g_X[(size_t)M_TOTAL * K_TOTAL];   // tf32-rounded X
__device__ float g_b[N_TOTAL];

__device__ __forceinline__ float rne_tf32(float f) {
    uint32_t r;
    asm("cvt.rna.tf32.f32 %0, %1;" : "=r"(r) : "f"(f));
    return __uint_as_float(r);
}

// ---------------------------------------------------------------------------
// Kernel 1: W = tf32(weight + sum_i (scale_i*wscale_i)*wq_i + (scale . wzp))
// ---------------------------------------------------------------------------
__global__ void compute_w_kernel(const float* __restrict__ weight,
                                 const int*   __restrict__ wq,
                                 const float* __restrict__ scale,
                                 const float* __restrict__ wscale,
                                 const int*   __restrict__ wzp) {
    const size_t nvec = (size_t)N_TOTAL * K_TOTAL / 4;
    size_t idx = (size_t)blockIdx.x * blockDim.x + threadIdx.x;
    if (idx >= nvec) return;

    float c[NSLOT];
    float z = 0.f;
#pragma unroll
    for (int i = 0; i < NSLOT; i++) {
        float s = scale[i];
        c[i] = s * wscale[i];
        z += s * (float)wzp[i];
    }
    float4 w = reinterpret_cast<const float4*>(weight)[idx];
    float ax = w.x + z, ay = w.y + z, az = w.z + z, aw = w.w + z;
#pragma unroll
    for (int i = 0; i < NSLOT; i++) {
        int4 q = reinterpret_cast<const int4*>(wq)[(size_t)i * nvec + idx];
        ax += c[i] * (float)q.x;
        ay += c[i] * (float)q.y;
        az += c[i] * (float)q.z;
        aw += c[i] * (float)q.w;
    }
    reinterpret_cast<float4*>(g_W)[idx] =
        make_float4(rne_tf32(ax), rne_tf32(ay), rne_tf32(az), rne_tf32(aw));
}

// ---------------------------------------------------------------------------
// Kernel 1b: X rounded to tf32 (zero CVTs in the GEMM mainloop)
// ---------------------------------------------------------------------------
__global__ void round_x_kernel(const float* __restrict__ x) {
    const size_t nvec = (size_t)M_TOTAL * K_TOTAL / 4;
    size_t idx = (size_t)blockIdx.x * blockDim.x + threadIdx.x;
    if (idx >= nvec) return;
    float4 v = reinterpret_cast<const float4*>(x)[idx];
    reinterpret_cast<float4*>(g_X)[idx] =
        make_float4(rne_tf32(v.x), rne_tf32(v.y), rne_tf32(v.z), rne_tf32(v.w));
}

// ---------------------------------------------------------------------------
// Kernel 2: b = bias + sum_i scale_i*(bscale_i*bq_i + bzp_i)
// ---------------------------------------------------------------------------
__global__ void compute_b_kernel(const float* __restrict__ bias,
                                 const float* __restrict__ scale,
                                 const int*   __restrict__ bq,
                                 const float* __restrict__ bscale,
                                 const int*   __restrict__ bzp) {
    int j = blockIdx.x * blockDim.x + threadIdx.x;
    if (j >= N_TOTAL) return;
    float acc = bias[j];
#pragma unroll
    for (int i = 0; i < NSLOT; i++)
        acc += scale[i] * (bscale[i] * (float)bq[i * N_TOTAL + j] + (float)bzp[i]);
    g_b[j] = acc;
}

// ---------------------------------------------------------------------------
// Kernel 3: OUT[m,n] = sum_k X[m,k] * W[n,k] + b[n]
// tf32 mma.sync m16n8k8. CTA 128x128x32, 4 warps (2x2), warp tile 64x64,
// 3-stage cp.async. 2 CTAs per SM (smem 110.6KB, regs <=256/thr).
// ---------------------------------------------------------------------------
extern __shared__ float smem_buf[];

__global__ void __launch_bounds__(128, 2)
gemm_tf32_kernel(float* __restrict__ OUT) {
    const int tid  = threadIdx.x;
    const int warp = tid >> 5;
    const int lane = tid & 31;
    const int wm = warp >> 1;   // 0..1 : 64 rows
    const int wn = warp & 1;    // 0..1 : 64 cols
    const int bm = blockIdx.y * BM;
    const int bn = blockIdx.x * BN;

    float* As = smem_buf;                         // STAGES * BM * TS
    float* Bs = smem_buf + STAGES * BM * TS;      // STAGES * BN * TS

    const int lrow = tid >> 3;        // 0..15
    const int lcol = (tid & 7) * 4;   // 0..28 step 4

    const float* a_base = g_X + (size_t)(bm + lrow) * K_TOTAL + lcol;
    const float* b_base = g_W + (size_t)(bn + lrow) * K_TOTAL + lcol;

    auto issue_tile = [&](int t) {
        const int s = t % STAGES;
        const size_t kofs = (size_t)t * BK;
        float* a_dst = As + s * BM * TS + lrow * TS + lcol;
        float* b_dst = Bs + s * BN * TS + lrow * TS + lcol;
        const float* a_src = a_base + kofs;
        const float* b_src = b_base + kofs;
#pragma unroll
        for (int p = 0; p < 8; p++) {
            uint32_t sa = (uint32_t)__cvta_generic_to_shared(a_dst + p * 16 * TS);
            asm volatile("cp.async.cg.shared.global [%0], [%1], 16;\n"
                         :: "r"(sa), "l"(a_src + (size_t)p * 16 * K_TOTAL));
        }
#pragma unroll
        for (int p = 0; p < 8; p++) {
            uint32_t sb = (uint32_t)__cvta_generic_to_shared(b_dst + p * 16 * TS);
            asm volatile("cp.async.cg.shared.global [%0], [%1], 16;\n"
                         :: "r"(sb), "l"(b_src + (size_t)p * 16 * K_TOTAL));
        }
    };

    float acc[4][8][4];
#pragma unroll
    for (int mt = 0; mt < 4; mt++)
#pragma unroll
        for (int nt = 0; nt < 8; nt++)
#pragma unroll
            for (int r = 0; r < 4; r++) acc[mt][nt][r] = 0.f;

    const int KT = K_TOTAL / BK;   // 128

#pragma unroll
    for (int t = 0; t < STAGES - 1; t++) {
        issue_tile(t);
        asm volatile("cp.async.commit_group;\n");
    }

    const int q = lane >> 2;   // 0..7
    const int c = lane & 3;    // 0..3

    for (int t = 0; t < KT; t++) {
        asm volatile("cp.async.wait_group %0;\n" :: "n"(STAGES - 2));
        __syncthreads();

        if (t + STAGES - 1 < KT) issue_tile(t + STAGES - 1);
        asm volatile("cp.async.commit_group;\n");

        const float* a_s = As + (t % STAGES) * BM * TS + (wm * 64) * TS;
        const float* b_s = Bs + (t % STAGES) * BN * TS + (wn * 64) * TS;

#pragma unroll
        for (int ks = 0; ks < 4; ks++) {
            const int k0 = ks * 8;
            uint32_t afr[4][4];
#pragma unroll
            for (int mt = 0; mt < 4; mt++) {
                const float* ap = a_s + (mt * 16 + q) * TS + k0 + c;
                afr[mt][0] = __float_as_uint(ap[0]);
                afr[mt][1] = __float_as_uint(ap[8 * TS]);
                afr[mt][2] = __float_as_uint(ap[4]);
                afr[mt][3] = __float_as_uint(ap[8 * TS + 4]);
            }
            uint32_t bfr[8][2];
#pragma unroll
            for (int nt = 0; nt < 8; nt++) {
                const float* bp = b_s + (nt * 8 + q) * TS + k0 + c;
                bfr[nt][0] = __float_as_uint(bp[0]);
                bfr[nt][1] = __float_as_uint(bp[4]);
            }
#pragma unroll
            for (int mt = 0; mt < 4; mt++) {
#pragma unroll
                for (int nt = 0; nt < 8; nt++) {
                    asm volatile(
                        "mma.sync.aligned.m16n8k8.row.col.f32.tf32.tf32.f32 "
                        "{%0,%1,%2,%3}, {%4,%5,%6,%7}, {%8,%9}, {%0,%1,%2,%3};\n"
                        : "+f"(acc[mt][nt][0]), "+f"(acc[mt][nt][1]),
                          "+f"(acc[mt][nt][2]), "+f"(acc[mt][nt][3])
                        : "r"(afr[mt][0]), "r"(afr[mt][1]),
                          "r"(afr[mt][2]), "r"(afr[mt][3]),
                          "r"(bfr[nt][0]), "r"(bfr[nt][1]));
                }
            }
        }
        __syncthreads();
    }

    // epilogue: bias + store (C fragment layout of m16n8)
#pragma unroll
    for (int mt = 0; mt < 4; mt++) {
        const int row0 = bm + wm * 64 + mt * 16 + q;
#pragma unroll
        for (int nt = 0; nt < 8; nt++) {
            const int col = bn + wn * 64 + nt * 8 + c * 2;
            const float b0 = g_b[col];
            const float b1 = g_b[col + 1];
            float2 v0 = make_float2(acc[mt][nt][0] + b0, acc[mt][nt][1] + b1);
            float2 v1 = make_float2(acc[mt][nt][2] + b0, acc[mt][nt][3] + b1);
            *reinterpret_cast<float2*>(OUT + (size_t)row0 * N_TOTAL + col) = v0;
            *reinterpret_cast<float2*>(OUT + (size_t)(row0 + 8) * N_TOTAL + col) = v1;
        }
    }
}

// ---------------------------------------------------------------------------
extern "C" void kernel_launch(void* const* d_in, const int* in_sizes, int n_in,
                              void* d_out, int out_size) {
    const float* x      = (const float*)d_in[0];
    const float* weight = (const float*)d_in[1];
    const float* bias   = (const float*)d_in[2];
    const float* scale  = (const float*)d_in[3];
    const int*   wq     = (const int*)  d_in[4];
    const float* wscale = (const float*)d_in[5];
    const int*   wzp    = (const int*)  d_in[6];
    const int*   bq     = (const int*)  d_in[7];
    const float* bscale = (const float*)d_in[8];
    const int*   bzp    = (const int*)  d_in[9];
    float* out = (float*)d_out;

    {
        const size_t nvec = (size_t)N_TOTAL * K_TOTAL / 4;
        compute_w_kernel<<<(int)((nvec + 255) / 256), 256>>>(weight, wq, scale, wscale, wzp);
    }
    {
        const size_t nvec = (size_t)M_TOTAL * K_TOTAL / 4;
        round_x_kernel<<<(int)((nvec + 255) / 256), 256>>>(x);
    }
    compute_b_kernel<<<(N_TOTAL + 255) / 256, 256>>>(bias, scale, bq, bscale, bzp);

    {
        int smem_bytes = STAGES * (BM + BN) * TS * (int)sizeof(float);  // 110592
        cudaFuncSetAttribute(gemm_tf32_kernel,
                             cudaFuncAttributeMaxDynamicSharedMemorySize, smem_bytes);
        dim3 grid(N_TOTAL / BN, M_TOTAL / BM);   // (32, 128)
        gemm_tf32_kernel<<<grid, 128, smem_bytes>>>(out);
    }
}

// round 5
// speedup vs baseline: 1.1866x; 1.1097x over previous
#include <cuda_runtime.h>
#include <cuda_fp16.h>
#include <cstdint>

#define M_TOTAL 16384
#define N_TOTAL 4096
#define K_TOTAL 4096
#define NSLOT   8

#define BM 128
#define BN 128
#define BK 64                 // fp16 elements per k-tile (128B per row)
#define STAGES 3
#define PADH 8
#define TSH (BK + PADH)       // 72 halves per smem row = 144B (conflict-free)

// Scratch (allocation-free rule: __device__ globals)
__device__ __half g_W[(size_t)N_TOTAL * K_TOTAL];   // dequantized fp16 W
__device__ __half g_X[(size_t)M_TOTAL * K_TOTAL];   // fp16 X
__device__ float  g_b[N_TOTAL];

// ---------------------------------------------------------------------------
// Kernel 1: W = fp16(weight + sum_i (scale_i*wscale_i)*wq_i + (scale . wzp))
// ---------------------------------------------------------------------------
__global__ void compute_w_kernel(const float* __restrict__ weight,
                                 const int*   __restrict__ wq,
                                 const float* __restrict__ scale,
                                 const float* __restrict__ wscale,
                                 const int*   __restrict__ wzp) {
    const size_t nvec = (size_t)N_TOTAL * K_TOTAL / 4;
    size_t idx = (size_t)blockIdx.x * blockDim.x + threadIdx.x;
    if (idx >= nvec) return;

    float c[NSLOT];
    float z = 0.f;
#pragma unroll
    for (int i = 0; i < NSLOT; i++) {
        float s = scale[i];
        c[i] = s * wscale[i];
        z += s * (float)wzp[i];
    }
    float4 w = reinterpret_cast<const float4*>(weight)[idx];
    float ax = w.x + z, ay = w.y + z, az = w.z + z, aw = w.w + z;
#pragma unroll
    for (int i = 0; i < NSLOT; i++) {
        int4 q = reinterpret_cast<const int4*>(wq)[(size_t)i * nvec + idx];
        ax += c[i] * (float)q.x;
        ay += c[i] * (float)q.y;
        az += c[i] * (float)q.z;
        aw += c[i] * (float)q.w;
    }
    __half2 lo = __floats2half2_rn(ax, ay);
    __half2 hi = __floats2half2_rn(az, aw);
    reinterpret_cast<uint2*>(g_W)[idx] =
        make_uint2(*reinterpret_cast<uint32_t*>(&lo), *reinterpret_cast<uint32_t*>(&hi));
}

// ---------------------------------------------------------------------------
// Kernel 1b: X -> fp16
// ---------------------------------------------------------------------------
__global__ void round_x_kernel(const float* __restrict__ x) {
    const size_t nvec = (size_t)M_TOTAL * K_TOTAL / 4;
    size_t idx = (size_t)blockIdx.x * blockDim.x + threadIdx.x;
    if (idx >= nvec) return;
    float4 v = reinterpret_cast<const float4*>(x)[idx];
    __half2 lo = __floats2half2_rn(v.x, v.y);
    __half2 hi = __floats2half2_rn(v.z, v.w);
    reinterpret_cast<uint2*>(g_X)[idx] =
        make_uint2(*reinterpret_cast<uint32_t*>(&lo), *reinterpret_cast<uint32_t*>(&hi));
}

// ---------------------------------------------------------------------------
// Kernel 2: b = bias + sum_i scale_i*(bscale_i*bq_i + bzp_i)
// ---------------------------------------------------------------------------
__global__ void compute_b_kernel(const float* __restrict__ bias,
                                 const float* __restrict__ scale,
                                 const int*   __restrict__ bq,
                                 const float* __restrict__ bscale,
                                 const int*   __restrict__ bzp) {
    int j = blockIdx.x * blockDim.x + threadIdx.x;
    if (j >= N_TOTAL) return;
    float acc = bias[j];
#pragma unroll
    for (int i = 0; i < NSLOT; i++)
        acc += scale[i] * (bscale[i] * (float)bq[i * N_TOTAL + j] + (float)bzp[i]);
    g_b[j] = acc;
}

// ---------------------------------------------------------------------------
// Kernel 3: OUT[m,n] = sum_k X[m,k] * W[n,k] + b[n]
// fp16 mma.sync m16n8k16 (fp32 accum). CTA 128x128x64, 4 warps (2x2),
// warp tile 64x64, 3-stage cp.async. 2 CTAs/SM (smem 110.6KB).
// ---------------------------------------------------------------------------
extern __shared__ __half smem_h[];

__global__ void __launch_bounds__(128, 2)
gemm_fp16_kernel(float* __restrict__ OUT) {
    const int tid  = threadIdx.x;
    const int warp = tid >> 5;
    const int lane = tid & 31;
    const int wm = warp >> 1;   // 0..1 : 64 rows
    const int wn = warp & 1;    // 0..1 : 64 cols
    const int bm = blockIdx.y * BM;
    const int bn = blockIdx.x * BN;

    __half* As = smem_h;                          // STAGES * BM * TSH halves
    __half* Bs = smem_h + STAGES * BM * TSH;      // STAGES * BN * TSH halves

    // producers: thread tid owns A row tid and B row tid (128B each per k-tile)
    const __half* a_src0 = g_X + (size_t)(bm + tid) * K_TOTAL;
    const __half* b_src0 = g_W + (size_t)(bn + tid) * K_TOTAL;

    auto issue_tile = [&](int t) {
        const int s = t % STAGES;
        const int kofs = t * BK;
        __half* a_dst = As + s * BM * TSH + tid * TSH;
        __half* b_dst = Bs + s * BN * TSH + tid * TSH;
        const __half* a_src = a_src0 + kofs;
        const __half* b_src = b_src0 + kofs;
#pragma unroll
        for (int p = 0; p < 8; p++) {
            uint32_t sa = (uint32_t)__cvta_generic_to_shared(a_dst + p * 8);
            asm volatile("cp.async.cg.shared.global [%0], [%1], 16;\n"
                         :: "r"(sa), "l"(a_src + p * 8));
        }
#pragma unroll
        for (int p = 0; p < 8; p++) {
            uint32_t sb = (uint32_t)__cvta_generic_to_shared(b_dst + p * 8);
            asm volatile("cp.async.cg.shared.global [%0], [%1], 16;\n"
                         :: "r"(sb), "l"(b_src + p * 8));
        }
    };

    float acc[4][8][4];
#pragma unroll
    for (int mt = 0; mt < 4; mt++)
#pragma unroll
        for (int nt = 0; nt < 8; nt++)
#pragma unroll
            for (int r = 0; r < 4; r++) acc[mt][nt][r] = 0.f;

    const int KT = K_TOTAL / BK;   // 64

#pragma unroll
    for (int t = 0; t < STAGES - 1; t++) {
        issue_tile(t);
        asm volatile("cp.async.commit_group;\n");
    }

    const int q = lane >> 2;   // 0..7 (row within 8)
    const int c = lane & 3;    // 0..3 (k pair index)

    for (int t = 0; t < KT; t++) {
        asm volatile("cp.async.wait_group %0;\n" :: "n"(STAGES - 2));
        __syncthreads();

        if (t + STAGES - 1 < KT) issue_tile(t + STAGES - 1);
        asm volatile("cp.async.commit_group;\n");

        const __half* a_s = As + (t % STAGES) * BM * TSH + (wm * 64) * TSH;
        const __half* b_s = Bs + (t % STAGES) * BN * TSH + (wn * 64) * TSH;

#pragma unroll
        for (int ks = 0; ks < 4; ks++) {
            const int k0 = ks * 16;
            uint32_t afr[4][4];
#pragma unroll
            for (int mt = 0; mt < 4; mt++) {
                const __half* ap = a_s + (mt * 16 + q) * TSH + k0 + 2 * c;
                afr[mt][0] = *reinterpret_cast<const uint32_t*>(ap);
                afr[mt][1] = *reinterpret_cast<const uint32_t*>(ap + 8 * TSH);
                afr[mt][2] = *reinterpret_cast<const uint32_t*>(ap + 8);
                afr[mt][3] = *reinterpret_cast<const uint32_t*>(ap + 8 * TSH + 8);
            }
            uint32_t bfr[8][2];
#pragma unroll
            for (int nt = 0; nt < 8; nt++) {
                const __half* bp = b_s + (nt * 8 + q) * TSH + k0 + 2 * c;
                bfr[nt][0] = *reinterpret_cast<const uint32_t*>(bp);
                bfr[nt][1] = *reinterpret_cast<const uint32_t*>(bp + 8);
            }
#pragma unroll
            for (int mt = 0; mt < 4; mt++) {
#pragma unroll
                for (int nt = 0; nt < 8; nt++) {
                    asm volatile(
                        "mma.sync.aligned.m16n8k16.row.col.f32.f16.f16.f32 "
                        "{%0,%1,%2,%3}, {%4,%5,%6,%7}, {%8,%9}, {%0,%1,%2,%3};\n"
                        : "+f"(acc[mt][nt][0]), "+f"(acc[mt][nt][1]),
                          "+f"(acc[mt][nt][2]), "+f"(acc[mt][nt][3])
                        : "r"(afr[mt][0]), "r"(afr[mt][1]),
                          "r"(afr[mt][2]), "r"(afr[mt][3]),
                          "r"(bfr[nt][0]), "r"(bfr[nt][1]));
                }
            }
        }
        __syncthreads();
    }

    // epilogue: bias + store (C fragment layout of m16n8)
#pragma unroll
    for (int mt = 0; mt < 4; mt++) {
        const int row0 = bm + wm * 64 + mt * 16 + q;
#pragma unroll
        for (int nt = 0; nt < 8; nt++) {
            const int col = bn + wn * 64 + nt * 8 + c * 2;
            const float b0 = g_b[col];
            const float b1 = g_b[col + 1];
            float2 v0 = make_float2(acc[mt][nt][0] + b0, acc[mt][nt][1] + b1);
            float2 v1 = make_float2(acc[mt][nt][2] + b0, acc[mt][nt][3] + b1);
            *reinterpret_cast<float2*>(OUT + (size_t)row0 * N_TOTAL + col) = v0;
            *reinterpret_cast<float2*>(OUT + (size_t)(row0 + 8) * N_TOTAL + col) = v1;
        }
    }
}

// ---------------------------------------------------------------------------
extern "C" void kernel_launch(void* const* d_in, const int* in_sizes, int n_in,
                              void* d_out, int out_size) {
    const float* x      = (const float*)d_in[0];
    const float* weight = (const float*)d_in[1];
    const float* bias   = (const float*)d_in[2];
    const float* scale  = (const float*)d_in[3];
    const int*   wq     = (const int*)  d_in[4];
    const float* wscale = (const float*)d_in[5];
    const int*   wzp    = (const int*)  d_in[6];
    const int*   bq     = (const int*)  d_in[7];
    const float* bscale = (const float*)d_in[8];
    const int*   bzp    = (const int*)  d_in[9];
    float* out = (float*)d_out;

    {
        const size_t nvec = (size_t)N_TOTAL * K_TOTAL / 4;
        compute_w_kernel<<<(int)((nvec + 255) / 256), 256>>>(weight, wq, scale, wscale, wzp);
    }
    {
        const size_t nvec = (size_t)M_TOTAL * K_TOTAL / 4;
        round_x_kernel<<<(int)((nvec + 255) / 256), 256>>>(x);
    }
    compute_b_kernel<<<(N_TOTAL + 255) / 256, 256>>>(bias, scale, bq, bscale, bzp);

    {
        int smem_bytes = STAGES * (BM + BN) * TSH * (int)sizeof(__half);  // 110592
        cudaFuncSetAttribute(gemm_fp16_kernel,
                             cudaFuncAttributeMaxDynamicSharedMemorySize, smem_bytes);
        dim3 grid(N_TOTAL / BN, M_TOTAL / BM);   // (32, 128)
        gemm_fp16_kernel<<<grid, 128, smem_bytes>>>(out);
    }
}

// round 6
// speedup vs baseline: 1.2817x; 1.0802x over previous
#include <cuda_runtime.h>
#include <cuda_fp16.h>
#include <cstdint>

#define M_TOTAL 16384
#define N_TOTAL 4096
#define K_TOTAL 4096
#define NSLOT   8

#define BM 128
#define BN 128
#define BK 64                 // fp16 elements per k-tile
#define STAGES 3
#define PADH 8
#define TSH (BK + PADH)       // 72 halves per smem row = 144B
#define ROWB (TSH * 2)        // 144 bytes per smem row

// Scratch (allocation-free rule: __device__ globals)
__device__ __half g_W[(size_t)N_TOTAL * K_TOTAL];
__device__ __half g_X[(size_t)M_TOTAL * K_TOTAL];
__device__ float  g_b[N_TOTAL];

// ---------------------------------------------------------------------------
// Kernel 1: W = fp16(weight + sum_i (scale_i*wscale_i)*wq_i + (scale . wzp))
// ---------------------------------------------------------------------------
__global__ void compute_w_kernel(const float* __restrict__ weight,
                                 const int*   __restrict__ wq,
                                 const float* __restrict__ scale,
                                 const float* __restrict__ wscale,
                                 const int*   __restrict__ wzp) {
    const size_t nvec = (size_t)N_TOTAL * K_TOTAL / 4;
    size_t idx = (size_t)blockIdx.x * blockDim.x + threadIdx.x;
    if (idx >= nvec) return;

    float c[NSLOT];
    float z = 0.f;
#pragma unroll
    for (int i = 0; i < NSLOT; i++) {
        float s = scale[i];
        c[i] = s * wscale[i];
        z += s * (float)wzp[i];
    }
    float4 w = reinterpret_cast<const float4*>(weight)[idx];
    float ax = w.x + z, ay = w.y + z, az = w.z + z, aw = w.w + z;
#pragma unroll
    for (int i = 0; i < NSLOT; i++) {
        int4 q = reinterpret_cast<const int4*>(wq)[(size_t)i * nvec + idx];
        ax += c[i] * (float)q.x;
        ay += c[i] * (float)q.y;
        az += c[i] * (float)q.z;
        aw += c[i] * (float)q.w;
    }
    __half2 lo = __floats2half2_rn(ax, ay);
    __half2 hi = __floats2half2_rn(az, aw);
    reinterpret_cast<uint2*>(g_W)[idx] =
        make_uint2(*reinterpret_cast<uint32_t*>(&lo), *reinterpret_cast<uint32_t*>(&hi));
}

// ---------------------------------------------------------------------------
// Kernel 1b: X -> fp16
// ---------------------------------------------------------------------------
__global__ void round_x_kernel(const float* __restrict__ x) {
    const size_t nvec = (size_t)M_TOTAL * K_TOTAL / 4;
    size_t idx = (size_t)blockIdx.x * blockDim.x + threadIdx.x;
    if (idx >= nvec) return;
    float4 v = reinterpret_cast<const float4*>(x)[idx];
    __half2 lo = __floats2half2_rn(v.x, v.y);
    __half2 hi = __floats2half2_rn(v.z, v.w);
    reinterpret_cast<uint2*>(g_X)[idx] =
        make_uint2(*reinterpret_cast<uint32_t*>(&lo), *reinterpret_cast<uint32_t*>(&hi));
}

// ---------------------------------------------------------------------------
// Kernel 2: b = bias + sum_i scale_i*(bscale_i*bq_i + bzp_i)
// ---------------------------------------------------------------------------
__global__ void compute_b_kernel(const float* __restrict__ bias,
                                 const float* __restrict__ scale,
                                 const int*   __restrict__ bq,
                                 const float* __restrict__ bscale,
                                 const int*   __restrict__ bzp) {
    int j = blockIdx.x * blockDim.x + threadIdx.x;
    if (j >= N_TOTAL) return;
    float acc = bias[j];
#pragma unroll
    for (int i = 0; i < NSLOT; i++)
        acc += scale[i] * (bscale[i] * (float)bq[i * N_TOTAL + j] + (float)bzp[i]);
    g_b[j] = acc;
}

// ---------------------------------------------------------------------------
// Kernel 3: fp16 m16n8k16 GEMM with ldmatrix fragment loads.
// CTA 128x128x64, 4 warps (2x2), warp tile 64x64, 3-stage cp.async,
// 2 CTAs/SM.
// ---------------------------------------------------------------------------
extern __shared__ __half smem_h[];

__global__ void __launch_bounds__(128, 2)
gemm_fp16_kernel(float* __restrict__ OUT) {
    const int tid  = threadIdx.x;
    const int warp = tid >> 5;
    const int lane = tid & 31;
    const int wm = warp >> 1;   // 0..1 : 64 rows
    const int wn = warp & 1;    // 0..1 : 64 cols
    const int bm = blockIdx.y * BM;
    const int bn = blockIdx.x * BN;

    __half* As = smem_h;
    __half* Bs = smem_h + STAGES * BM * TSH;

    const uint32_t As_u = (uint32_t)__cvta_generic_to_shared(As);
    const uint32_t Bs_u = (uint32_t)__cvta_generic_to_shared(Bs);

    // producers: thread tid owns A row tid and B row tid
    const __half* a_src0 = g_X + (size_t)(bm + tid) * K_TOTAL;
    const __half* b_src0 = g_W + (size_t)(bn + tid) * K_TOTAL;

    auto issue_tile = [&](int t) {
        const int s = t % STAGES;
        const int kofs = t * BK;
        uint32_t a_dst = As_u + (s * BM + tid) * ROWB;
        uint32_t b_dst = Bs_u + (s * BN + tid) * ROWB;
        const __half* a_src = a_src0 + kofs;
        const __half* b_src = b_src0 + kofs;
#pragma unroll
        for (int p = 0; p < 8; p++)
            asm volatile("cp.async.cg.shared.global [%0], [%1], 16;\n"
                         :: "r"(a_dst + p * 16), "l"(a_src + p * 8));
#pragma unroll
        for (int p = 0; p < 8; p++)
            asm volatile("cp.async.cg.shared.global [%0], [%1], 16;\n"
                         :: "r"(b_dst + p * 16), "l"(b_src + p * 8));
    };

    float acc[4][8][4];
#pragma unroll
    for (int mt = 0; mt < 4; mt++)
#pragma unroll
        for (int nt = 0; nt < 8; nt++)
#pragma unroll
            for (int r = 0; r < 4; r++) acc[mt][nt][r] = 0.f;

    const int KT = K_TOTAL / BK;   // 64

#pragma unroll
    for (int t = 0; t < STAGES - 1; t++) {
        issue_tile(t);
        asm volatile("cp.async.commit_group;\n");
    }

    // ldmatrix per-lane offsets (bytes, within stage):
    // A x4: lanes 0-15 -> rows (lane&15) @ k0 ; lanes 16-31 -> same rows @ +16B
    const uint32_t a_lm = (uint32_t)((wm * 64 + (lane & 15)) * ROWB + (lane >> 4) * 16);
    // B x4 (two n8 tiles): lanes 0-7 n0-7@k0, 8-15 n0-7@+16B, 16-23 n8-15@k0, 24-31 n8-15@+16B
    const uint32_t b_lm = (uint32_t)((wn * 64 + ((lane >> 4) * 8 + (lane & 7))) * ROWB
                                     + ((lane >> 3) & 1) * 16);

    const int q = lane >> 2;   // epilogue row helper
    const int c = lane & 3;

    for (int t = 0; t < KT; t++) {
        asm volatile("cp.async.wait_group %0;\n" :: "n"(STAGES - 2));
        __syncthreads();

        if (t + STAGES - 1 < KT) issue_tile(t + STAGES - 1);
        asm volatile("cp.async.commit_group;\n");

        const int s = t % STAGES;
        const uint32_t aS = As_u + s * BM * ROWB + a_lm;
        const uint32_t bS = Bs_u + s * BN * ROWB + b_lm;

#pragma unroll
        for (int ks = 0; ks < 4; ks++) {
            const uint32_t kb = ks * 32;   // 16 halves = 32 bytes
            uint32_t afr[4][4];
#pragma unroll
            for (int mt = 0; mt < 4; mt++) {
                asm volatile(
                    "ldmatrix.sync.aligned.m8n8.x4.shared.b16 {%0,%1,%2,%3}, [%4];"
                    : "=r"(afr[mt][0]), "=r"(afr[mt][1]),
                      "=r"(afr[mt][2]), "=r"(afr[mt][3])
                    : "r"(aS + mt * 16 * ROWB + kb));
            }
            uint32_t bfr[8][2];
#pragma unroll
            for (int pr = 0; pr < 4; pr++) {
                asm volatile(
                    "ldmatrix.sync.aligned.m8n8.x4.shared.b16 {%0,%1,%2,%3}, [%4];"
                    : "=r"(bfr[2 * pr][0]), "=r"(bfr[2 * pr][1]),
                      "=r"(bfr[2 * pr + 1][0]), "=r"(bfr[2 * pr + 1][1])
                    : "r"(bS + pr * 16 * ROWB + kb));
            }
#pragma unroll
            for (int mt = 0; mt < 4; mt++) {
#pragma unroll
                for (int nt = 0; nt < 8; nt++) {
                    asm volatile(
                        "mma.sync.aligned.m16n8k16.row.col.f32.f16.f16.f32 "
                        "{%0,%1,%2,%3}, {%4,%5,%6,%7}, {%8,%9}, {%0,%1,%2,%3};\n"
                        : "+f"(acc[mt][nt][0]), "+f"(acc[mt][nt][1]),
                          "+f"(acc[mt][nt][2]), "+f"(acc[mt][nt][3])
                        : "r"(afr[mt][0]), "r"(afr[mt][1]),
                          "r"(afr[mt][2]), "r"(afr[mt][3]),
                          "r"(bfr[nt][0]), "r"(bfr[nt][1]));
                }
            }
        }
        __syncthreads();
    }

    // epilogue: bias + store (C fragment layout of m16n8)
#pragma unroll
    for (int mt = 0; mt < 4; mt++) {
        const int row0 = bm + wm * 64 + mt * 16 + q;
#pragma unroll
        for (int nt = 0; nt < 8; nt++) {
            const int col = bn + wn * 64 + nt * 8 + c * 2;
            const float b0 = g_b[col];
            const float b1 = g_b[col + 1];
            float2 v0 = make_float2(acc[mt][nt][0] + b0, acc[mt][nt][1] + b1);
            float2 v1 = make_float2(acc[mt][nt][2] + b0, acc[mt][nt][3] + b1);
            *reinterpret_cast<float2*>(OUT + (size_t)row0 * N_TOTAL + col) = v0;
            *reinterpret_cast<float2*>(OUT + (size_t)(row0 + 8) * N_TOTAL + col) = v1;
        }
    }
}

// ---------------------------------------------------------------------------
extern "C" void kernel_launch(void* const* d_in, const int* in_sizes, int n_in,
                              void* d_out, int out_size) {
    const float* x      = (const float*)d_in[0];
    const float* weight = (const float*)d_in[1];
    const float* bias   = (const float*)d_in[2];
    const float* scale  = (const float*)d_in[3];
    const int*   wq     = (const int*)  d_in[4];
    const float* wscale = (const float*)d_in[5];
    const int*   wzp    = (const int*)  d_in[6];
    const int*   bq     = (const int*)  d_in[7];
    const float* bscale = (const float*)d_in[8];
    const int*   bzp    = (const int*)  d_in[9];
    float* out = (float*)d_out;

    {
        const size_t nvec = (size_t)N_TOTAL * K_TOTAL / 4;
        compute_w_kernel<<<(int)((nvec + 255) / 256), 256>>>(weight, wq, scale, wscale, wzp);
    }
    {
        const size_t nvec = (size_t)M_TOTAL * K_TOTAL / 4;
        round_x_kernel<<<(int)((nvec + 255) / 256), 256>>>(x);
    }
    compute_b_kernel<<<(N_TOTAL + 255) / 256, 256>>>(bias, scale, bq, bscale, bzp);

    {
        int smem_bytes = STAGES * (BM + BN) * TSH * (int)sizeof(__half);  // 110592
        cudaFuncSetAttribute(gemm_fp16_kernel,
                             cudaFuncAttributeMaxDynamicSharedMemorySize, smem_bytes);
        dim3 grid(N_TOTAL / BN, M_TOTAL / BM);   // (32, 128)
        gemm_fp16_kernel<<<grid, 128, smem_bytes>>>(out);
    }
}

// round 7
// speedup vs baseline: 1.3485x; 1.0521x over previous
#include <cuda_runtime.h>
#include <cuda_fp16.h>
#include <cstdint>

#define M_TOTAL 16384
#define N_TOTAL 4096
#define K_TOTAL 4096
#define NSLOT   8

#define BM 128
#define BN 128
#define BK 64
#define STAGES 3
#define PADH 8
#define TSH (BK + PADH)       // 72 halves per smem row
#define ROWB (TSH * 2)        // 144 bytes per smem row

// Scratch (allocation-free rule: __device__ globals)
__device__ __half g_W[(size_t)N_TOTAL * K_TOTAL];
__device__ __half g_X[(size_t)M_TOTAL * K_TOTAL];
__device__ float  g_b[N_TOTAL];

// ---------------------------------------------------------------------------
// Kernel 1: W = fp16(weight + sum_i (scale_i*wscale_i)*wq_i + (scale . wzp))
// ---------------------------------------------------------------------------
__global__ void compute_w_kernel(const float* __restrict__ weight,
                                 const int*   __restrict__ wq,
                                 const float* __restrict__ scale,
                                 const float* __restrict__ wscale,
                                 const int*   __restrict__ wzp) {
    const size_t nvec = (size_t)N_TOTAL * K_TOTAL / 4;
    size_t idx = (size_t)blockIdx.x * blockDim.x + threadIdx.x;
    if (idx >= nvec) return;

    float c[NSLOT];
    float z = 0.f;
#pragma unroll
    for (int i = 0; i < NSLOT; i++) {
        float s = scale[i];
        c[i] = s * wscale[i];
        z += s * (float)wzp[i];
    }
    float4 w = reinterpret_cast<const float4*>(weight)[idx];
    float ax = w.x + z, ay = w.y + z, az = w.z + z, aw = w.w + z;
#pragma unroll
    for (int i = 0; i < NSLOT; i++) {
        int4 q = reinterpret_cast<const int4*>(wq)[(size_t)i * nvec + idx];
        ax += c[i] * (float)q.x;
        ay += c[i] * (float)q.y;
        az += c[i] * (float)q.z;
        aw += c[i] * (float)q.w;
    }
    __half2 lo = __floats2half2_rn(ax, ay);
    __half2 hi = __floats2half2_rn(az, aw);
    reinterpret_cast<uint2*>(g_W)[idx] =
        make_uint2(*reinterpret_cast<uint32_t*>(&lo), *reinterpret_cast<uint32_t*>(&hi));
}

// ---------------------------------------------------------------------------
// Kernel 1b: X -> fp16
// ---------------------------------------------------------------------------
__global__ void round_x_kernel(const float* __restrict__ x) {
    const size_t nvec = (size_t)M_TOTAL * K_TOTAL / 4;
    size_t idx = (size_t)blockIdx.x * blockDim.x + threadIdx.x;
    if (idx >= nvec) return;
    float4 v = reinterpret_cast<const float4*>(x)[idx];
    __half2 lo = __floats2half2_rn(v.x, v.y);
    __half2 hi = __floats2half2_rn(v.z, v.w);
    reinterpret_cast<uint2*>(g_X)[idx] =
        make_uint2(*reinterpret_cast<uint32_t*>(&lo), *reinterpret_cast<uint32_t*>(&hi));
}

// ---------------------------------------------------------------------------
// Kernel 2: b = bias + sum_i scale_i*(bscale_i*bq_i + bzp_i)
// ---------------------------------------------------------------------------
__global__ void compute_b_kernel(const float* __restrict__ bias,
                                 const float* __restrict__ scale,
                                 const int*   __restrict__ bq,
                                 const float* __restrict__ bscale,
                                 const int*   __restrict__ bzp) {
    int j = blockIdx.x * blockDim.x + threadIdx.x;
    if (j >= N_TOTAL) return;
    float acc = bias[j];
#pragma unroll
    for (int i = 0; i < NSLOT; i++)
        acc += scale[i] * (bscale[i] * (float)bq[i * N_TOTAL + j] + (float)bzp[i]);
    g_b[j] = acc;
}

// ---------------------------------------------------------------------------
// Kernel 3: fp16 m16n8k16 GEMM, ldmatrix + double-buffered fragments,
// one barrier per k-tile. CTA 128x128x64, 4 warps (2x2), warp 64x64,
// 3-stage cp.async, 2 CTAs/SM.
// ---------------------------------------------------------------------------
extern __shared__ __half smem_h[];

__global__ void __launch_bounds__(128, 2)
gemm_fp16_kernel(float* __restrict__ OUT) {
    const int tid  = threadIdx.x;
    const int warp = tid >> 5;
    const int lane = tid & 31;
    const int wm = warp >> 1;
    const int wn = warp & 1;
    const int bm = blockIdx.y * BM;
    const int bn = blockIdx.x * BN;

    __half* As = smem_h;
    __half* Bs = smem_h + STAGES * BM * TSH;

    const uint32_t As_u = (uint32_t)__cvta_generic_to_shared(As);
    const uint32_t Bs_u = (uint32_t)__cvta_generic_to_shared(Bs);

    const __half* a_src0 = g_X + (size_t)(bm + tid) * K_TOTAL;
    const __half* b_src0 = g_W + (size_t)(bn + tid) * K_TOTAL;

    auto issue_tile = [&](int t) {
        const int s = t % STAGES;
        const int kofs = t * BK;
        uint32_t a_dst = As_u + (s * BM + tid) * ROWB;
        uint32_t b_dst = Bs_u + (s * BN + tid) * ROWB;
        const __half* a_src = a_src0 + kofs;
        const __half* b_src = b_src0 + kofs;
#pragma unroll
        for (int p = 0; p < 8; p++)
            asm volatile("cp.async.cg.shared.global [%0], [%1], 16;\n"
                         :: "r"(a_dst + p * 16), "l"(a_src + p * 8));
#pragma unroll
        for (int p = 0; p < 8; p++)
            asm volatile("cp.async.cg.shared.global [%0], [%1], 16;\n"
                         :: "r"(b_dst + p * 16), "l"(b_src + p * 8));
    };

    float acc[4][8][4];
#pragma unroll
    for (int mt = 0; mt < 4; mt++)
#pragma unroll
        for (int nt = 0; nt < 8; nt++)
#pragma unroll
            for (int r = 0; r < 4; r++) acc[mt][nt][r] = 0.f;

    const int KT = K_TOTAL / BK;   // 64

#pragma unroll
    for (int t = 0; t < STAGES - 1; t++) {
        issue_tile(t);
        asm volatile("cp.async.commit_group;\n");
    }

    // ldmatrix per-lane base offsets (bytes within a stage)
    const uint32_t a_lm = (uint32_t)((wm * 64 + (lane & 15)) * ROWB + (lane >> 4) * 16);
    const uint32_t b_lm = (uint32_t)((wn * 64 + ((lane >> 4) * 8 + (lane & 7))) * ROWB
                                     + ((lane >> 3) & 1) * 16);

    const int q = lane >> 2;
    const int c = lane & 3;

    uint32_t afr[2][4][4];
    uint32_t bfr[2][8][2];

    auto load_frag = [&](uint32_t aS, uint32_t bS, int ks, int buf) {
        const uint32_t kb = (uint32_t)ks * 32;
#pragma unroll
        for (int mt = 0; mt < 4; mt++) {
            asm volatile(
                "ldmatrix.sync.aligned.m8n8.x4.shared.b16 {%0,%1,%2,%3}, [%4];"
                : "=r"(afr[buf][mt][0]), "=r"(afr[buf][mt][1]),
                  "=r"(afr[buf][mt][2]), "=r"(afr[buf][mt][3])
                : "r"(aS + mt * 16 * ROWB + kb));
        }
#pragma unroll
        for (int pr = 0; pr < 4; pr++) {
            asm volatile(
                "ldmatrix.sync.aligned.m8n8.x4.shared.b16 {%0,%1,%2,%3}, [%4];"
                : "=r"(bfr[buf][2 * pr][0]), "=r"(bfr[buf][2 * pr][1]),
                  "=r"(bfr[buf][2 * pr + 1][0]), "=r"(bfr[buf][2 * pr + 1][1])
                : "r"(bS + pr * 16 * ROWB + kb));
        }
    };

    auto mma_step = [&](int buf) {
#pragma unroll
        for (int mt = 0; mt < 4; mt++) {
#pragma unroll
            for (int nt = 0; nt < 8; nt++) {
                asm volatile(
                    "mma.sync.aligned.m16n8k16.row.col.f32.f16.f16.f32 "
                    "{%0,%1,%2,%3}, {%4,%5,%6,%7}, {%8,%9}, {%0,%1,%2,%3};\n"
                    : "+f"(acc[mt][nt][0]), "+f"(acc[mt][nt][1]),
                      "+f"(acc[mt][nt][2]), "+f"(acc[mt][nt][3])
                    : "r"(afr[buf][mt][0]), "r"(afr[buf][mt][1]),
                      "r"(afr[buf][mt][2]), "r"(afr[buf][mt][3]),
                      "r"(bfr[buf][nt][0]), "r"(bfr[buf][nt][1]));
            }
        }
    };

    for (int t = 0; t < KT; t++) {
        asm volatile("cp.async.wait_group %0;\n" :: "n"(STAGES - 2));
        __syncthreads();

        const int s = t % STAGES;
        const uint32_t aS = As_u + s * BM * ROWB + a_lm;
        const uint32_t bS = Bs_u + s * BN * ROWB + b_lm;

        // load ks=0 fragments first (needed immediately)
        load_frag(aS, bS, 0, 0);

        // then kick off the prefetch for tile t+2 (2 tiles of slack)
        if (t + STAGES - 1 < KT) issue_tile(t + STAGES - 1);
        asm volatile("cp.async.commit_group;\n");

#pragma unroll
        for (int ks = 0; ks < 4; ks++) {
            if (ks < 3) load_frag(aS, bS, ks + 1, (ks + 1) & 1);
            mma_step(ks & 1);
        }
    }

    // epilogue: bias + store (C fragment layout of m16n8)
#pragma unroll
    for (int mt = 0; mt < 4; mt++) {
        const int row0 = bm + wm * 64 + mt * 16 + q;
#pragma unroll
        for (int nt = 0; nt < 8; nt++) {
            const int col = bn + wn * 64 + nt * 8 + c * 2;
            const float b0 = g_b[col];
            const float b1 = g_b[col + 1];
            float2 v0 = make_float2(acc[mt][nt][0] + b0, acc[mt][nt][1] + b1);
            float2 v1 = make_float2(acc[mt][nt][2] + b0, acc[mt][nt][3] + b1);
            *reinterpret_cast<float2*>(OUT + (size_t)row0 * N_TOTAL + col) = v0;
            *reinterpret_cast<float2*>(OUT + (size_t)(row0 + 8) * N_TOTAL + col) = v1;
        }
    }
}

// ---------------------------------------------------------------------------
extern "C" void kernel_launch(void* const* d_in, const int* in_sizes, int n_in,
                              void* d_out, int out_size) {
    const float* x      = (const float*)d_in[0];
    const float* weight = (const float*)d_in[1];
    const float* bias   = (const float*)d_in[2];
    const float* scale  = (const float*)d_in[3];
    const int*   wq     = (const int*)  d_in[4];
    const float* wscale = (const float*)d_in[5];
    const int*   wzp    = (const int*)  d_in[6];
    const int*   bq     = (const int*)  d_in[7];
    const float* bscale = (const float*)d_in[8];
    const int*   bzp    = (const int*)  d_in[9];
    float* out = (float*)d_out;

    {
        const size_t nvec = (size_t)N_TOTAL * K_TOTAL / 4;
        compute_w_kernel<<<(int)((nvec + 255) / 256), 256>>>(weight, wq, scale, wscale, wzp);
    }
    {
        const size_t nvec = (size_t)M_TOTAL * K_TOTAL / 4;
        round_x_kernel<<<(int)((nvec + 255) / 256), 256>>>(x);
    }
    compute_b_kernel<<<(N_TOTAL + 255) / 256, 256>>>(bias, scale, bq, bscale, bzp);

    {
        int smem_bytes = STAGES * (BM + BN) * TSH * (int)sizeof(__half);  // 110592
        cudaFuncSetAttribute(gemm_fp16_kernel,
                             cudaFuncAttributeMaxDynamicSharedMemorySize, smem_bytes);
        dim3 grid(N_TOTAL / BN, M_TOTAL / BM);   // (32, 128)
        gemm_fp16_kernel<<<grid, 128, smem_bytes>>>(out);
    }
}

// round 9
// speedup vs baseline: 1.5335x; 1.1372x over previous
#include <cuda_runtime.h>
#include <cuda_fp16.h>
#include <cstdint>

#define M_TOTAL 16384
#define N_TOTAL 4096
#define K_TOTAL 4096
#define NSLOT   8

#define BM 128
#define BN 128
#define BK 64
#define STAGES 3
#define PADH 8
#define TSH (BK + PADH)       // 72 halves per smem row
#define ROWB (TSH * 2)        // 144 bytes per smem row

// Scratch (allocation-free rule: __device__ globals)
__device__ __half g_W[(size_t)N_TOTAL * K_TOTAL];
__device__ __half g_X[(size_t)M_TOTAL * K_TOTAL];
__device__ float  g_b[N_TOTAL];

// ---------------------------------------------------------------------------
// Kernel 1: W = fp16(weight + sum_i (scale_i*wscale_i)*wq_i + (scale . wzp))
// ---------------------------------------------------------------------------
__global__ void compute_w_kernel(const float* __restrict__ weight,
                                 const int*   __restrict__ wq,
                                 const float* __restrict__ scale,
                                 const float* __restrict__ wscale,
                                 const int*   __restrict__ wzp) {
    const size_t nvec = (size_t)N_TOTAL * K_TOTAL / 4;
    size_t idx = (size_t)blockIdx.x * blockDim.x + threadIdx.x;
    if (idx >= nvec) return;

    float c[NSLOT];
    float z = 0.f;
#pragma unroll
    for (int i = 0; i < NSLOT; i++) {
        float s = scale[i];
        c[i] = s * wscale[i];
        z += s * (float)wzp[i];
    }
    float4 w = reinterpret_cast<const float4*>(weight)[idx];
    float ax = w.x + z, ay = w.y + z, az = w.z + z, aw = w.w + z;
#pragma unroll
    for (int i = 0; i < NSLOT; i++) {
        int4 q = reinterpret_cast<const int4*>(wq)[(size_t)i * nvec + idx];
        ax += c[i] * (float)q.x;
        ay += c[i] * (float)q.y;
        az += c[i] * (float)q.z;
        aw += c[i] * (float)q.w;
    }
    __half2 lo = __floats2half2_rn(ax, ay);
    __half2 hi = __floats2half2_rn(az, aw);
    reinterpret_cast<uint2*>(g_W)[idx] =
        make_uint2(*reinterpret_cast<uint32_t*>(&lo), *reinterpret_cast<uint32_t*>(&hi));
}

// ---------------------------------------------------------------------------
// Kernel 1b: X -> fp16
// ---------------------------------------------------------------------------
__global__ void round_x_kernel(const float* __restrict__ x) {
    const size_t nvec = (size_t)M_TOTAL * K_TOTAL / 4;
    size_t idx = (size_t)blockIdx.x * blockDim.x + threadIdx.x;
    if (idx >= nvec) return;
    float4 v = reinterpret_cast<const float4*>(x)[idx];
    __half2 lo = __floats2half2_rn(v.x, v.y);
    __half2 hi = __floats2half2_rn(v.z, v.w);
    reinterpret_cast<uint2*>(g_X)[idx] =
        make_uint2(*reinterpret_cast<uint32_t*>(&lo), *reinterpret_cast<uint32_t*>(&hi));
}

// ---------------------------------------------------------------------------
// Kernel 2: b = bias + sum_i scale_i*(bscale_i*bq_i + bzp_i)
// ---------------------------------------------------------------------------
__global__ void compute_b_kernel(const float* __restrict__ bias,
                                 const float* __restrict__ scale,
                                 const int*   __restrict__ bq,
                                 const float* __restrict__ bscale,
                                 const int*   __restrict__ bzp) {
    int j = blockIdx.x * blockDim.x + threadIdx.x;
    if (j >= N_TOTAL) return;
    float acc = bias[j];
#pragma unroll
    for (int i = 0; i < NSLOT; i++)
        acc += scale[i] * (bscale[i] * (float)bq[i * N_TOTAL + j] + (float)bzp[i]);
    g_b[j] = acc;
}

// ---------------------------------------------------------------------------
// Kernel 3: fp16 m16n8k16 GEMM, ldmatrix, 8 warps (2x4), warp tile 64x32,
// CTA 128x128x64, 3-stage cp.async, 2 CTAs/SM => 4 warps/SMSP.
// ---------------------------------------------------------------------------
extern __shared__ __half smem_h[];

__global__ void __launch_bounds__(256, 2)
gemm_fp16_kernel(float* __restrict__ OUT) {
    const int tid  = threadIdx.x;
    const int warp = tid >> 5;
    const int lane = tid & 31;
    const int wm = warp >> 2;   // 0..1 : 64 rows
    const int wn = warp & 3;    // 0..3 : 32 cols
    const int bm = blockIdx.y * BM;
    const int bn = blockIdx.x * BN;

    __half* As = smem_h;
    __half* Bs = smem_h + STAGES * BM * TSH;

    const uint32_t As_u = (uint32_t)__cvta_generic_to_shared(As);
    const uint32_t Bs_u = (uint32_t)__cvta_generic_to_shared(Bs);

    // producers: 256 threads, each owns HALF a row's k-tile data:
    // 64 bytes = 32 halves (row data per k-tile = BK*2 = 128 bytes).
    const int prow = tid >> 1;          // 0..127
    const int pcol = (tid & 1) * 32;    // element offset within k-tile
    const __half* a_src0 = g_X + (size_t)(bm + prow) * K_TOTAL + pcol;
    const __half* b_src0 = g_W + (size_t)(bn + prow) * K_TOTAL + pcol;
    const uint32_t pdst = prow * ROWB + (tid & 1) * 64;   // byte offset in row

    auto issue_tile = [&](int t) {
        const int s = t % STAGES;
        const int kofs = t * BK;
        uint32_t a_dst = As_u + s * BM * ROWB + pdst;
        uint32_t b_dst = Bs_u + s * BN * ROWB + pdst;
        const __half* a_src = a_src0 + kofs;
        const __half* b_src = b_src0 + kofs;
#pragma unroll
        for (int p = 0; p < 4; p++)
            asm volatile("cp.async.cg.shared.global [%0], [%1], 16;\n"
                         :: "r"(a_dst + p * 16), "l"(a_src + p * 8));
#pragma unroll
        for (int p = 0; p < 4; p++)
            asm volatile("cp.async.cg.shared.global [%0], [%1], 16;\n"
                         :: "r"(b_dst + p * 16), "l"(b_src + p * 8));
    };

    float acc[4][4][4];
#pragma unroll
    for (int mt = 0; mt < 4; mt++)
#pragma unroll
        for (int nt = 0; nt < 4; nt++)
#pragma unroll
            for (int r = 0; r < 4; r++) acc[mt][nt][r] = 0.f;

    const int KT = K_TOTAL / BK;   // 64

#pragma unroll
    for (int t = 0; t < STAGES - 1; t++) {
        issue_tile(t);
        asm volatile("cp.async.commit_group;\n");
    }

    // ldmatrix per-lane base offsets (bytes within a stage)
    const uint32_t a_lm = (uint32_t)((wm * 64 + (lane & 15)) * ROWB + (lane >> 4) * 16);
    const uint32_t b_lm = (uint32_t)((wn * 32 + ((lane >> 4) * 8 + (lane & 7))) * ROWB
                                     + ((lane >> 3) & 1) * 16);

    const int q = lane >> 2;
    const int c = lane & 3;

    for (int t = 0; t < KT; t++) {
        asm volatile("cp.async.wait_group %0;\n" :: "n"(STAGES - 2));
        __syncthreads();

        if (t + STAGES - 1 < KT) issue_tile(t + STAGES - 1);
        asm volatile("cp.async.commit_group;\n");

        const int s = t % STAGES;
        const uint32_t aS = As_u + s * BM * ROWB + a_lm;
        const uint32_t bS = Bs_u + s * BN * ROWB + b_lm;

#pragma unroll
        for (int ks = 0; ks < 4; ks++) {
            const uint32_t kb = (uint32_t)ks * 32;
            uint32_t afr[4][4];
#pragma unroll
            for (int mt = 0; mt < 4; mt++) {
                asm volatile(
                    "ldmatrix.sync.aligned.m8n8.x4.shared.b16 {%0,%1,%2,%3}, [%4];"
                    : "=r"(afr[mt][0]), "=r"(afr[mt][1]),
                      "=r"(afr[mt][2]), "=r"(afr[mt][3])
                    : "r"(aS + mt * 16 * ROWB + kb));
            }
            uint32_t bfr[4][2];
#pragma unroll
            for (int pr = 0; pr < 2; pr++) {
                asm volatile(
                    "ldmatrix.sync.aligned.m8n8.x4.shared.b16 {%0,%1,%2,%3}, [%4];"
                    : "=r"(bfr[2 * pr][0]), "=r"(bfr[2 * pr][1]),
                      "=r"(bfr[2 * pr + 1][0]), "=r"(bfr[2 * pr + 1][1])
                    : "r"(bS + pr * 16 * ROWB + kb));
            }
#pragma unroll
            for (int mt = 0; mt < 4; mt++) {
#pragma unroll
                for (int nt = 0; nt < 4; nt++) {
                    asm volatile(
                        "mma.sync.aligned.m16n8k16.row.col.f32.f16.f16.f32 "
                        "{%0,%1,%2,%3}, {%4,%5,%6,%7}, {%8,%9}, {%0,%1,%2,%3};\n"
                        : "+f"(acc[mt][nt][0]), "+f"(acc[mt][nt][1]),
                          "+f"(acc[mt][nt][2]), "+f"(acc[mt][nt][3])
                        : "r"(afr[mt][0]), "r"(afr[mt][1]),
                          "r"(afr[mt][2]), "r"(afr[mt][3]),
                          "r"(bfr[nt][0]), "r"(bfr[nt][1]));
                }
            }
        }
        __syncthreads();
    }

    // epilogue: bias + store (C fragment layout of m16n8)
#pragma unroll
    for (int mt = 0; mt < 4; mt++) {
        const int row0 = bm + wm * 64 + mt * 16 + q;
#pragma unroll
        for (int nt = 0; nt < 4; nt++) {
            const int col = bn + wn * 32 + nt * 8 + c * 2;
            const float b0 = g_b[col];
            const float b1 = g_b[col + 1];
            float2 v0 = make_float2(acc[mt][nt][0] + b0, acc[mt][nt][1] + b1);
            float2 v1 = make_float2(acc[mt][nt][2] + b0, acc[mt][nt][3] + b1);
            *reinterpret_cast<float2*>(OUT + (size_t)row0 * N_TOTAL + col) = v0;
            *reinterpret_cast<float2*>(OUT + (size_t)(row0 + 8) * N_TOTAL + col) = v1;
        }
    }
}

// ---------------------------------------------------------------------------
extern "C" void kernel_launch(void* const* d_in, const int* in_sizes, int n_in,
                              void* d_out, int out_size) {
    const float* x      = (const float*)d_in[0];
    const float* weight = (const float*)d_in[1];
    const float* bias   = (const float*)d_in[2];
    const float* scale  = (const float*)d_in[3];
    const int*   wq     = (const int*)  d_in[4];
    const float* wscale = (const float*)d_in[5];
    const int*   wzp    = (const int*)  d_in[6];
    const int*   bq     = (const int*)  d_in[7];
    const float* bscale = (const float*)d_in[8];
    const int*   bzp    = (const int*)  d_in[9];
    float* out = (float*)d_out;

    {
        const size_t nvec = (size_t)N_TOTAL * K_TOTAL / 4;
        compute_w_kernel<<<(int)((nvec + 255) / 256), 256>>>(weight, wq, scale, wscale, wzp);
    }
    {
        const size_t nvec = (size_t)M_TOTAL * K_TOTAL / 4;
        round_x_kernel<<<(int)((nvec + 255) / 256), 256>>>(x);
    }
    compute_b_kernel<<<(N_TOTAL + 255) / 256, 256>>>(bias, scale, bq, bscale, bzp);

    {
        int smem_bytes = STAGES * (BM + BN) * TSH * (int)sizeof(__half);  // 110592
        cudaFuncSetAttribute(gemm_fp16_kernel,
                             cudaFuncAttributeMaxDynamicSharedMemorySize, smem_bytes);
        dim3 grid(N_TOTAL / BN, M_TOTAL / BM);   // (32, 128)
        gemm_fp16_kernel<<<grid, 256, smem_bytes>>>(out);
    }
}